// round 6
// baseline (speedup 1.0000x reference)
#include <cuda_runtime.h>
#include <cuda_bf16.h>
#include <math_constants.h>
#include <cstdint>

#define BATCH 8192
#define DIM   512
#define T_INV 14.2857142857142857f  // 1/0.07

#define NSPLIT 16
#define TPC    4
#define MT     128
#define NT     128
#define KC     64                  // bf16 halves per chunk
#define NCHUNK (DIM / KC)          // 8
#define NSTAGE 3

#define PITCHH 72                  // halves per SMEM row (144B; conflict-free frags)
#define PITCH32 (PITCHH / 2)       // 36 uint32 per row
#define AB_HALVES (MT * PITCHH)            // 9216 halves = 18432 B per operand
#define STAGE_HALVES (2 * AB_HALVES)
#define STAGE_BYTES  (STAGE_HALVES * 2)    // 36864
#define SMEM_BYTES   (NSTAGE * STAGE_BYTES) // 110592 (C tile + partials alias)
#define CPITCH 132

// ---------------- static scratch ----------------
__device__ __nv_bfloat16 g_fb[BATCH * DIM];
__device__ int   g_idx[BATCH];
__device__ unsigned g_Gkey;
__device__ float g_pS[NSPLIT * BATCH], g_pP[NSPLIT * BATCH];
__device__ float g_pn[NSPLIT * BATCH], g_prm[NSPLIT * BATCH];
__device__ float g_pt[NSPLIT * BATCH * 5];
__device__ float g_D1[BATCH], g_H[BATCH], g_B[BATCH];

// ---------------- helpers ----------------
__device__ __forceinline__ uint32_t smem_u32(const void* p) {
    uint32_t a;
    asm("{ .reg .u64 t; cvta.to.shared.u64 t, %1; cvt.u32.u64 %0, t; }" : "=r"(a) : "l"(p));
    return a;
}
__device__ __forceinline__ void cpa16(uint32_t dst, const void* src) {
    asm volatile("cp.async.cg.shared.global [%0], [%1], 16;" :: "r"(dst), "l"(src));
}
#define CP_COMMIT() asm volatile("cp.async.commit_group;" ::: "memory")
#define CP_WAIT1()  asm volatile("cp.async.wait_group 1;" ::: "memory")
#define CP_WAIT0()  asm volatile("cp.async.wait_group 0;" ::: "memory")

__device__ __forceinline__ void mma16(float* c, const uint32_t* a, uint32_t b0, uint32_t b1) {
    asm volatile(
        "mma.sync.aligned.m16n8k16.row.col.f32.bf16.bf16.f32 "
        "{%0,%1,%2,%3}, {%4,%5,%6,%7}, {%8,%9}, {%0,%1,%2,%3};"
        : "+f"(c[0]), "+f"(c[1]), "+f"(c[2]), "+f"(c[3])
        : "r"(a[0]), "r"(a[1]), "r"(a[2]), "r"(a[3]), "r"(b0), "r"(b1));
}

__device__ __forceinline__ unsigned fkey(float f) {
    unsigned u = __float_as_uint(f);
    return (u & 0x80000000u) ? ~u : (u | 0x80000000u);
}
__device__ __forceinline__ float funkey(unsigned k) {
    unsigned u = (k & 0x80000000u) ? (k & 0x7FFFFFFFu) : ~k;
    return __uint_as_float(u);
}
__device__ __forceinline__ void top5_ins(float v, float& t0, float& t1, float& t2,
                                         float& t3, float& t4) {
    if (v > t4) {
        float w = v, tmp;
        if (w > t0) { tmp = t0; t0 = w; w = tmp; }
        if (w > t1) { tmp = t1; t1 = w; w = tmp; }
        if (w > t2) { tmp = t2; t2 = w; w = tmp; }
        if (w > t3) { tmp = t3; t3 = w; w = tmp; }
        t4 = w;
    }
}

// ---------------------------------------------------------------------------
// Kernel 0: dtype-agnostic index canonicalization (int32 vs int64) + G reset
// ---------------------------------------------------------------------------
__global__ void prep_idx_kernel(const int* __restrict__ raw) {
    __shared__ int sh[256];
    int tid = threadIdx.x;
    int acc = 0;
    for (int i = tid; i < BATCH / 2; i += 256) acc |= raw[2 * i + 1];
    sh[tid] = acc;
    __syncthreads();
    for (int s = 128; s; s >>= 1) { if (tid < s) sh[tid] |= sh[tid + s]; __syncthreads(); }
    bool is64 = (sh[0] == 0);
    for (int i = tid; i < BATCH; i += 256) g_idx[i] = is64 ? raw[2 * i] : raw[i];
    if (tid == 0) g_Gkey = 0u;
}

// ---------------------------------------------------------------------------
// Kernel 1: L2 normalize + round to bf16 (rn)
// ---------------------------------------------------------------------------
__global__ void normalize_kernel(const float* __restrict__ x) {
    int row = blockIdx.x;
    int t = threadIdx.x;
    float4 v = ((const float4*)(x + row * DIM))[t];
    float ss = v.x * v.x + v.y * v.y + v.z * v.z + v.w * v.w;
    #pragma unroll
    for (int o = 16; o; o >>= 1) ss += __shfl_xor_sync(0xffffffffu, ss, o);
    __shared__ float ws[4];
    if ((t & 31) == 0) ws[t >> 5] = ss;
    __syncthreads();
    float inv = 1.0f / fmaxf(sqrtf(ws[0] + ws[1] + ws[2] + ws[3]), 1e-12f);
    __nv_bfloat162 p0 = __floats2bfloat162_rn(v.x * inv, v.y * inv);
    __nv_bfloat162 p1 = __floats2bfloat162_rn(v.z * inv, v.w * inv);
    uint2 w;
    w.x = *(uint32_t*)&p0;
    w.y = *(uint32_t*)&p1;
    ((uint2*)(g_fb + row * DIM))[t] = w;
}

// ---------------------------------------------------------------------------
// Kernel 2: HMMA bf16 sim GEMM (cp.async 3-stage, 1 sync/chunk) + fused scan
//   grid = 64 strips x 16 splits; block = 256 (8 warps, 4x2 of 32x64 tiles)
// ---------------------------------------------------------------------------
__device__ __forceinline__ void prefetch_chunk(uint32_t s_base, int st, int row0,
                                               int col0, int kb, int tid) {
    const uint32_t stf = s_base + st * STAGE_BYTES;
    #pragma unroll
    for (int i = tid; i < MT * 8; i += 256) {       // A: 128 rows x 8 segs of 16B
        int r = i >> 3, sg = i & 7;
        cpa16(stf + (r * PITCHH + sg * 8) * 2, g_fb + (row0 + r) * DIM + kb + sg * 8);
    }
    #pragma unroll
    for (int i = tid; i < NT * 8; i += 256) {       // B
        int r = i >> 3, sg = i & 7;
        cpa16(stf + AB_HALVES * 2 + (r * PITCHH + sg * 8) * 2,
              g_fb + (col0 + r) * DIM + kb + sg * 8);
    }
    CP_COMMIT();
}

__global__ __launch_bounds__(256, 2)
void sim_kernel() {
    extern __shared__ float smem[];
    const uint32_t s_base = smem_u32(smem);
    const int tid  = threadIdx.x;
    const int lane = tid & 31, warp = tid >> 5;
    const int strip = blockIdx.x >> 4;
    const int split = blockIdx.x & (NSPLIT - 1);
    const int row0 = strip * MT;
    const int wm = warp >> 1, wn = warp & 1;
    const int qg = lane >> 2, qt = lane & 3;

    // persistent per-row scan state (row = row0 + (tid & 127))
    float S = 0.f, P = 0.f, n = 0.f, rm = -CUDART_INF_F;
    float t0 = -CUDART_INF_F, t1 = -CUDART_INF_F, t2 = -CUDART_INF_F,
          t3 = -CUDART_INF_F, t4 = -CUDART_INF_F;
    const int srow = tid & 127, shalf = tid >> 7;
    const int myrow = row0 + srow;
    const int myidx = g_idx[myrow];

    for (int tile = 0; tile < TPC; tile++) {
        const int col0 = split * (TPC * NT) + tile * NT;
        float acc[2][8][4];
        #pragma unroll
        for (int i = 0; i < 2; i++)
            #pragma unroll
            for (int j = 0; j < 8; j++)
                #pragma unroll
                for (int q = 0; q < 4; q++) acc[i][j][q] = 0.f;

        prefetch_chunk(s_base, 0, row0, col0, 0, tid);
        prefetch_chunk(s_base, 1, row0, col0, KC, tid);

        for (int c = 0; c < NCHUNK; c++) {
            const int st = c % NSTAGE;
            if (c == NCHUNK - 1) { CP_WAIT0(); } else { CP_WAIT1(); }
            __syncthreads();   // stage c ready; stage (c+2)%3 fully consumed (chunk c-1)
            if (c + 2 < NCHUNK)
                prefetch_chunk(s_base, (c + 2) % NSTAGE, row0, col0, (c + 2) * KC, tid);

            const uint32_t* As = (const uint32_t*)smem + st * (STAGE_HALVES / 2);
            const uint32_t* Bs = As + AB_HALVES / 2;
            const uint32_t* apb = As + (wm * 32 + qg) * PITCH32 + qt;
            const uint32_t* bpb = Bs + (wn * 64 + qg) * PITCH32 + qt;
            #pragma unroll
            for (int ks = 0; ks < 4; ks++) {
                const int kk2 = ks * 8;   // u32 offset of this k16 step
                uint32_t a[2][4];
                #pragma unroll
                for (int i = 0; i < 2; i++) {
                    const uint32_t* ap = apb + i * 16 * PITCH32 + kk2;
                    a[i][0] = ap[0];
                    a[i][1] = ap[8 * PITCH32];
                    a[i][2] = ap[4];
                    a[i][3] = ap[8 * PITCH32 + 4];
                }
                #pragma unroll
                for (int j = 0; j < 8; j++) {
                    const uint32_t* bp = bpb + j * 8 * PITCH32 + kk2;
                    uint32_t b0 = bp[0];
                    uint32_t b1 = bp[4];
                    mma16(acc[0][j], a[0], b0, b1);
                    mma16(acc[1][j], a[1], b0, b1);
                }
            }
        }
        __syncthreads();   // all mma LDS reads done before C tile overwrites stages

        // stage C tile (aliases stage buffers)
        float* Cs = smem;
        float* Ps = smem + 128 * CPITCH;    // 128 rows x 9 partial floats
        #pragma unroll
        for (int i = 0; i < 2; i++) {
            #pragma unroll
            for (int j = 0; j < 8; j++) {
                int r = wm * 32 + i * 16 + qg;
                int cc = wn * 64 + j * 8 + 2 * qt;
                Cs[r * CPITCH + cc]           = acc[i][j][0];
                Cs[r * CPITCH + cc + 1]       = acc[i][j][1];
                Cs[(r + 8) * CPITCH + cc]     = acc[i][j][2];
                Cs[(r + 8) * CPITCH + cc + 1] = acc[i][j][3];
            }
        }
        __syncthreads();

        // split scan: each row handled by 2 threads (64 cols each)
        {
            const float* crow = Cs + srow * CPITCH + shalf * 64;
            const int colbase = col0 + shalf * 64;
            float lS = 0.f, lP = 0.f, ln = 0.f, lrm = -CUDART_INF_F;
            float l0 = -CUDART_INF_F, l1 = -CUDART_INF_F, l2 = -CUDART_INF_F,
                  l3 = -CUDART_INF_F, l4 = -CUDART_INF_F;
            for (int cc = 0; cc < 64; cc++) {
                int gcol = colbase + cc;
                if (gcol == myrow) continue;
                float v = crow[cc];
                top5_ins(v, l0, l1, l2, l3, l4);
                if (__ldg(&g_idx[gcol]) == myidx) {
                    ln += 1.0f; lS += v; lrm = fmaxf(lrm, v);
                    lP += __expf(v * T_INV);
                }
            }
            if (shalf) {
                float* pp = Ps + srow * 9;
                pp[0] = lS; pp[1] = lP; pp[2] = ln; pp[3] = lrm;
                pp[4] = l0; pp[5] = l1; pp[6] = l2; pp[7] = l3; pp[8] = l4;
            } else {
                S += lS; P += lP; n += ln; rm = fmaxf(rm, lrm);
                top5_ins(l0, t0, t1, t2, t3, t4);
                top5_ins(l1, t0, t1, t2, t3, t4);
                top5_ins(l2, t0, t1, t2, t3, t4);
                top5_ins(l3, t0, t1, t2, t3, t4);
                top5_ins(l4, t0, t1, t2, t3, t4);
            }
            __syncthreads();
            if (!shalf) {
                const float* pp = Ps + srow * 9;
                S += pp[0]; P += pp[1]; n += pp[2]; rm = fmaxf(rm, pp[3]);
                top5_ins(pp[4], t0, t1, t2, t3, t4);
                top5_ins(pp[5], t0, t1, t2, t3, t4);
                top5_ins(pp[6], t0, t1, t2, t3, t4);
                top5_ins(pp[7], t0, t1, t2, t3, t4);
                top5_ins(pp[8], t0, t1, t2, t3, t4);
            }
        }
        __syncthreads();   // scans done before next tile's prefetch overwrites
    }

    if (tid < 128) {
        int base = split * BATCH + myrow;
        g_pS[base] = S; g_pP[base] = P; g_pn[base] = n; g_prm[base] = rm;
        float* tp = g_pt + (size_t)base * 5;
        tp[0] = t0; tp[1] = t1; tp[2] = t2; tp[3] = t3; tp[4] = t4;
    }
}

// ---------------------------------------------------------------------------
// Kernel 3: merge partials; compute per-row terms; deterministic global max
// ---------------------------------------------------------------------------
__global__ void merge_kernel() {
    int r = blockIdx.x * 256 + threadIdx.x;
    float S = 0.f, P = 0.f, n = 0.f, rm = -CUDART_INF_F;
    float t0 = -CUDART_INF_F, t1 = -CUDART_INF_F, t2 = -CUDART_INF_F,
          t3 = -CUDART_INF_F, t4 = -CUDART_INF_F;
    #pragma unroll
    for (int s = 0; s < NSPLIT; s++) {
        int b = s * BATCH + r;
        S += g_pS[b]; P += g_pP[b]; n += g_pn[b]; rm = fmaxf(rm, g_prm[b]);
        const float* tp = g_pt + (size_t)b * 5;
        #pragma unroll
        for (int j = 0; j < 5; j++) top5_ins(tp[j], t0, t1, t2, t3, t4);
    }
    g_D1[r] = (n > 0.f) ? __expf(-rm * T_INV) * P : 0.f;
    g_H[r]  = __expf(t0 * T_INV) + __expf(t1 * T_INV) + __expf(t2 * T_INV) +
              __expf(t3 * T_INV) + __expf(t4 * T_INV);
    g_B[r]  = (n > 0.f) ? (S * T_INV) / n : 0.f;
    if (n <= 0.f) g_H[r] = -1.f;   // sentinel: row contributes 0

    __shared__ unsigned sm[256];
    sm[threadIdx.x] = fkey(t0);
    __syncthreads();
    for (int s = 128; s; s >>= 1) {
        if (threadIdx.x < s) sm[threadIdx.x] = max(sm[threadIdx.x], sm[threadIdx.x + s]);
        __syncthreads();
    }
    if (threadIdx.x == 0) atomicMax(&g_Gkey, sm[0]);
}

// ---------------------------------------------------------------------------
// Kernel 4: final loss
// ---------------------------------------------------------------------------
__global__ void finalize_kernel(float* __restrict__ out) {
    __shared__ float sh[1024];
    int tid = threadIdx.x;
    float G = funkey(g_Gkey) * T_INV;
    float eG = __expf(-G);
    float sum = 0.f;
    for (int r = tid; r < BATCH; r += 1024) {
        float H = g_H[r];
        if (H >= 0.f)
            sum += __logf(g_D1[r] + eG * H) - g_B[r];
    }
    sh[tid] = sum;
    __syncthreads();
    for (int s = 512; s; s >>= 1) {
        if (tid < s) sh[tid] += sh[tid + s];
        __syncthreads();
    }
    if (tid == 0) out[0] = sh[0] / (float)BATCH;
}

// ---------------------------------------------------------------------------
extern "C" void kernel_launch(void* const* d_in, const int* in_sizes, int n_in,
                              void* d_out, int out_size) {
    const float* x   = (const float*)d_in[0];
    const int*   idx = (const int*)d_in[1];
    float*       out = (float*)d_out;

    cudaFuncSetAttribute(sim_kernel, cudaFuncAttributeMaxDynamicSharedMemorySize,
                         SMEM_BYTES);

    prep_idx_kernel<<<1, 256>>>(idx);
    normalize_kernel<<<BATCH, 128>>>(x);
    sim_kernel<<<64 * NSPLIT, 256, SMEM_BYTES>>>();
    merge_kernel<<<BATCH / 256, 256>>>();
    finalize_kernel<<<1, 1024>>>(out);
}

// round 7
// speedup vs baseline: 1.3184x; 1.3184x over previous
#include <cuda_runtime.h>
#include <cuda_bf16.h>
#include <math_constants.h>
#include <cstdint>

#define BATCH 8192
#define DIM   512
#define T_INV 14.2857142857142857f  // 1/0.07

#define NSTRIP 64                  // 64 strips of 128 rows
#define NTILE  (NSTRIP * (NSTRIP + 1) / 2)   // 2080 upper-tri tiles
#define NSLOT  64
#define PSTRIDE 12                 // floats per partial record (9 used, f4-aligned)

#define MT     128
#define NT     128
#define KC     64                  // bf16 halves per chunk
#define NCHUNK (DIM / KC)          // 8

#define PITCHH 72                  // halves per SMEM row (144B; conflict-free frags)
#define PITCH32 (PITCHH / 2)       // 36 uint32 per row
#define AB_HALVES (MT * PITCHH)            // 9216 halves per operand
#define STAGE_HALVES (2 * AB_HALVES)
#define STAGE_BYTES  (STAGE_HALVES * 2)    // 36864
#define SMEM_BYTES   (2 * STAGE_BYTES)     // 73728 (C tile + partials alias)
#define CPITCH 132

// ---------------- static scratch ----------------
__device__ __nv_bfloat16 g_fb[BATCH * DIM];
__device__ int   g_idx[BATCH];
__device__ unsigned g_Gkey;
__device__ float g_part[(size_t)BATCH * NSLOT * PSTRIDE];  // per (row, slot) partials
__device__ float g_D1[BATCH], g_H[BATCH], g_B[BATCH];

// ---------------- helpers ----------------
__device__ __forceinline__ uint32_t smem_u32(const void* p) {
    uint32_t a;
    asm("{ .reg .u64 t; cvta.to.shared.u64 t, %1; cvt.u32.u64 %0, t; }" : "=r"(a) : "l"(p));
    return a;
}
__device__ __forceinline__ void cpa16(uint32_t dst, const void* src) {
    asm volatile("cp.async.cg.shared.global [%0], [%1], 16;" :: "r"(dst), "l"(src));
}
#define CP_COMMIT() asm volatile("cp.async.commit_group;" ::: "memory")
#define CP_WAIT1()  asm volatile("cp.async.wait_group 1;" ::: "memory")
#define CP_WAIT0()  asm volatile("cp.async.wait_group 0;" ::: "memory")

__device__ __forceinline__ void mma16(float* c, const uint32_t* a, uint32_t b0, uint32_t b1) {
    asm volatile(
        "mma.sync.aligned.m16n8k16.row.col.f32.bf16.bf16.f32 "
        "{%0,%1,%2,%3}, {%4,%5,%6,%7}, {%8,%9}, {%0,%1,%2,%3};"
        : "+f"(c[0]), "+f"(c[1]), "+f"(c[2]), "+f"(c[3])
        : "r"(a[0]), "r"(a[1]), "r"(a[2]), "r"(a[3]), "r"(b0), "r"(b1));
}

__device__ __forceinline__ unsigned fkey(float f) {
    unsigned u = __float_as_uint(f);
    return (u & 0x80000000u) ? ~u : (u | 0x80000000u);
}
__device__ __forceinline__ float funkey(unsigned k) {
    unsigned u = (k & 0x80000000u) ? (k & 0x7FFFFFFFu) : ~k;
    return __uint_as_float(u);
}
__device__ __forceinline__ void top5_ins(float v, float& t0, float& t1, float& t2,
                                         float& t3, float& t4) {
    if (v > t4) {
        float w = v, tmp;
        if (w > t0) { tmp = t0; t0 = w; w = tmp; }
        if (w > t1) { tmp = t1; t1 = w; w = tmp; }
        if (w > t2) { tmp = t2; t2 = w; w = tmp; }
        if (w > t3) { tmp = t3; t3 = w; w = tmp; }
        t4 = w;
    }
}

// ---------------------------------------------------------------------------
// Kernel 0: dtype-agnostic index canonicalization (int32 vs int64) + G reset
// ---------------------------------------------------------------------------
__global__ void prep_idx_kernel(const int* __restrict__ raw) {
    __shared__ int sh[256];
    int tid = threadIdx.x;
    int acc = 0;
    for (int i = tid; i < BATCH / 2; i += 256) acc |= raw[2 * i + 1];
    sh[tid] = acc;
    __syncthreads();
    for (int s = 128; s; s >>= 1) { if (tid < s) sh[tid] |= sh[tid + s]; __syncthreads(); }
    bool is64 = (sh[0] == 0);
    for (int i = tid; i < BATCH; i += 256) g_idx[i] = is64 ? raw[2 * i] : raw[i];
    if (tid == 0) g_Gkey = 0u;
}

// ---------------------------------------------------------------------------
// Kernel 1: L2 normalize + round to bf16 (rn)
// ---------------------------------------------------------------------------
__global__ void normalize_kernel(const float* __restrict__ x) {
    int row = blockIdx.x;
    int t = threadIdx.x;
    float4 v = ((const float4*)(x + row * DIM))[t];
    float ss = v.x * v.x + v.y * v.y + v.z * v.z + v.w * v.w;
    #pragma unroll
    for (int o = 16; o; o >>= 1) ss += __shfl_xor_sync(0xffffffffu, ss, o);
    __shared__ float ws[4];
    if ((t & 31) == 0) ws[t >> 5] = ss;
    __syncthreads();
    float inv = 1.0f / fmaxf(sqrtf(ws[0] + ws[1] + ws[2] + ws[3]), 1e-12f);
    __nv_bfloat162 p0 = __floats2bfloat162_rn(v.x * inv, v.y * inv);
    __nv_bfloat162 p1 = __floats2bfloat162_rn(v.z * inv, v.w * inv);
    uint2 w;
    w.x = *(uint32_t*)&p0;
    w.y = *(uint32_t*)&p1;
    ((uint2*)(g_fb + row * DIM))[t] = w;
}

// ---------------------------------------------------------------------------
// Kernel 2: symmetric-triangle HMMA bf16 GEMM + dual (row+col) fused scans
//   grid = 2080 upper-tri tiles; block = 256 (8 warps, 4x2 of 32x64 tiles)
// ---------------------------------------------------------------------------
__device__ __forceinline__ void prefetch_chunk(uint32_t s_base, int st, int row0,
                                               int col0, int kb, int tid) {
    const uint32_t stf = s_base + st * STAGE_BYTES;
    #pragma unroll
    for (int i = tid; i < MT * 8; i += 256) {       // A: 128 rows x 8 segs of 16B
        int r = i >> 3, sg = i & 7;
        cpa16(stf + (r * PITCHH + sg * 8) * 2, g_fb + (row0 + r) * DIM + kb + sg * 8);
    }
    #pragma unroll
    for (int i = tid; i < NT * 8; i += 256) {       // B
        int r = i >> 3, sg = i & 7;
        cpa16(stf + AB_HALVES * 2 + (r * PITCHH + sg * 8) * 2,
              g_fb + (col0 + r) * DIM + kb + sg * 8);
    }
    CP_COMMIT();
}

__global__ __launch_bounds__(256, 2)
void sim_kernel() {
    extern __shared__ float smem[];
    const uint32_t s_base = smem_u32(smem);
    const int tid  = threadIdx.x;
    const int lane = tid & 31, warp = tid >> 5;

    // decode blockIdx -> (I, J) with I <= J  (b = J(J+1)/2 + I)
    const int b = blockIdx.x;
    int J = (int)((sqrtf(8.0f * b + 1.0f) - 1.0f) * 0.5f);
    while ((J + 1) * (J + 2) / 2 <= b) ++J;
    while (J * (J + 1) / 2 > b) --J;
    const int I = b - J * (J + 1) / 2;
    const int row0 = I * MT;
    const int col0 = J * NT;

    const int wm = warp >> 1, wn = warp & 1;
    const int qg = lane >> 2, qt = lane & 3;

    float acc[2][8][4];
    #pragma unroll
    for (int i = 0; i < 2; i++)
        #pragma unroll
        for (int j = 0; j < 8; j++)
            #pragma unroll
            for (int q = 0; q < 4; q++) acc[i][j][q] = 0.f;

    prefetch_chunk(s_base, 0, row0, col0, 0, tid);
    prefetch_chunk(s_base, 1, row0, col0, KC, tid);

    for (int c = 0; c < NCHUNK; c++) {
        const int st = c & 1;
        if (c >= NCHUNK - 2) { CP_WAIT0(); } else { CP_WAIT1(); }
        __syncthreads();
        const uint32_t* As = (const uint32_t*)smem + st * (STAGE_HALVES / 2);
        const uint32_t* Bs = As + AB_HALVES / 2;
        const uint32_t* apb = As + (wm * 32 + qg) * PITCH32 + qt;
        const uint32_t* bpb = Bs + (wn * 64 + qg) * PITCH32 + qt;
        #pragma unroll
        for (int ks = 0; ks < 4; ks++) {
            const int kk2 = ks * 8;
            uint32_t a[2][4];
            #pragma unroll
            for (int i = 0; i < 2; i++) {
                const uint32_t* ap = apb + i * 16 * PITCH32 + kk2;
                a[i][0] = ap[0];
                a[i][1] = ap[8 * PITCH32];
                a[i][2] = ap[4];
                a[i][3] = ap[8 * PITCH32 + 4];
            }
            #pragma unroll
            for (int j = 0; j < 8; j++) {
                const uint32_t* bp = bpb + j * 8 * PITCH32 + kk2;
                uint32_t b0 = bp[0];
                uint32_t b1 = bp[4];
                mma16(acc[0][j], a[0], b0, b1);
                mma16(acc[1][j], a[1], b0, b1);
            }
        }
        __syncthreads();
        if (c + 2 < NCHUNK)
            prefetch_chunk(s_base, st, row0, col0, (c + 2) * KC, tid);
    }

    // stage C tile (aliases stage buffers; all mma LDS reads complete)
    float* Cs = smem;
    float* Ps = smem + 128 * CPITCH;    // 128 x 9 partial-exchange floats
    #pragma unroll
    for (int i = 0; i < 2; i++) {
        #pragma unroll
        for (int j = 0; j < 8; j++) {
            int r = wm * 32 + i * 16 + qg;
            int cc = wn * 64 + j * 8 + 2 * qt;
            Cs[r * CPITCH + cc]           = acc[i][j][0];
            Cs[r * CPITCH + cc + 1]       = acc[i][j][1];
            Cs[(r + 8) * CPITCH + cc]     = acc[i][j][2];
            Cs[(r + 8) * CPITCH + cc + 1] = acc[i][j][3];
        }
    }
    __syncthreads();

    const int sidx = tid & 127, shalf = tid >> 7;

    // ---- row scan: stats for strip I rows over strip J cols -> slot J ----
    {
        const int myrow = row0 + sidx;
        const int myidx = g_idx[myrow];
        const float* crow = Cs + sidx * CPITCH + shalf * 64;
        const int colbase = col0 + shalf * 64;
        float lS = 0.f, lP = 0.f, ln = 0.f, lrm = -CUDART_INF_F;
        float l0 = -CUDART_INF_F, l1 = -CUDART_INF_F, l2 = -CUDART_INF_F,
              l3 = -CUDART_INF_F, l4 = -CUDART_INF_F;
        for (int cc = 0; cc < 64; cc++) {
            int gcol = colbase + cc;
            if (gcol == myrow) continue;   // only possible on diagonal tiles
            float v = crow[cc];
            top5_ins(v, l0, l1, l2, l3, l4);
            if (__ldg(&g_idx[gcol]) == myidx) {
                ln += 1.0f; lS += v; lrm = fmaxf(lrm, v);
                lP += __expf(v * T_INV);
            }
        }
        if (shalf) {
            float* pp = Ps + sidx * 9;
            pp[0] = lS; pp[1] = lP; pp[2] = ln; pp[3] = lrm;
            pp[4] = l0; pp[5] = l1; pp[6] = l2; pp[7] = l3; pp[8] = l4;
        }
        __syncthreads();
        if (!shalf) {
            const float* pp = Ps + sidx * 9;
            lS += pp[0]; lP += pp[1]; ln += pp[2]; lrm = fmaxf(lrm, pp[3]);
            top5_ins(pp[4], l0, l1, l2, l3, l4);
            top5_ins(pp[5], l0, l1, l2, l3, l4);
            top5_ins(pp[6], l0, l1, l2, l3, l4);
            top5_ins(pp[7], l0, l1, l2, l3, l4);
            top5_ins(pp[8], l0, l1, l2, l3, l4);
            float* gp = g_part + ((size_t)myrow * NSLOT + J) * PSTRIDE;
            gp[0] = lS; gp[1] = lP; gp[2] = ln; gp[3] = lrm;
            gp[4] = l0; gp[5] = l1; gp[6] = l2; gp[7] = l3; gp[8] = l4;
        }
    }

    if (I == J) return;   // diagonal: row scan fully covers; no col scan

    __syncthreads();      // Ps reuse

    // ---- col scan: stats for strip J rows over strip I cols -> slot I ----
    {
        const int myrow = col0 + sidx;          // global row owned via tile col
        const int myidx = g_idx[myrow];
        const int rbase = shalf * 64;
        float lS = 0.f, lP = 0.f, ln = 0.f, lrm = -CUDART_INF_F;
        float l0 = -CUDART_INF_F, l1 = -CUDART_INF_F, l2 = -CUDART_INF_F,
              l3 = -CUDART_INF_F, l4 = -CUDART_INF_F;
        for (int rr = 0; rr < 64; rr++) {
            float v = Cs[(rbase + rr) * CPITCH + sidx];
            top5_ins(v, l0, l1, l2, l3, l4);
            if (__ldg(&g_idx[row0 + rbase + rr]) == myidx) {
                ln += 1.0f; lS += v; lrm = fmaxf(lrm, v);
                lP += __expf(v * T_INV);
            }
        }
        if (shalf) {
            float* pp = Ps + sidx * 9;
            pp[0] = lS; pp[1] = lP; pp[2] = ln; pp[3] = lrm;
            pp[4] = l0; pp[5] = l1; pp[6] = l2; pp[7] = l3; pp[8] = l4;
        }
        __syncthreads();
        if (!shalf) {
            const float* pp = Ps + sidx * 9;
            lS += pp[0]; lP += pp[1]; ln += pp[2]; lrm = fmaxf(lrm, pp[3]);
            top5_ins(pp[4], l0, l1, l2, l3, l4);
            top5_ins(pp[5], l0, l1, l2, l3, l4);
            top5_ins(pp[6], l0, l1, l2, l3, l4);
            top5_ins(pp[7], l0, l1, l2, l3, l4);
            top5_ins(pp[8], l0, l1, l2, l3, l4);
            float* gp = g_part + ((size_t)myrow * NSLOT + I) * PSTRIDE;
            gp[0] = lS; gp[1] = lP; gp[2] = ln; gp[3] = lrm;
            gp[4] = l0; gp[5] = l1; gp[6] = l2; gp[7] = l3; gp[8] = l4;
        }
    }
}

// ---------------------------------------------------------------------------
// Kernel 3: merge 64 slots per row (contiguous float4 reads); global max
// ---------------------------------------------------------------------------
__global__ void merge_kernel() {
    int r = blockIdx.x * 256 + threadIdx.x;
    const float4* base = (const float4*)(g_part + (size_t)r * NSLOT * PSTRIDE);
    float S = 0.f, P = 0.f, n = 0.f, rm = -CUDART_INF_F;
    float t0 = -CUDART_INF_F, t1 = -CUDART_INF_F, t2 = -CUDART_INF_F,
          t3 = -CUDART_INF_F, t4 = -CUDART_INF_F;
    #pragma unroll 4
    for (int s = 0; s < NSLOT; s++) {
        float4 a = base[s * 3 + 0];
        float4 c = base[s * 3 + 1];
        float4 d = base[s * 3 + 2];
        S += a.x; P += a.y; n += a.z; rm = fmaxf(rm, a.w);
        top5_ins(c.x, t0, t1, t2, t3, t4);
        top5_ins(c.y, t0, t1, t2, t3, t4);
        top5_ins(c.z, t0, t1, t2, t3, t4);
        top5_ins(c.w, t0, t1, t2, t3, t4);
        top5_ins(d.x, t0, t1, t2, t3, t4);
    }
    g_D1[r] = (n > 0.f) ? __expf(-rm * T_INV) * P : 0.f;
    g_H[r]  = __expf(t0 * T_INV) + __expf(t1 * T_INV) + __expf(t2 * T_INV) +
              __expf(t3 * T_INV) + __expf(t4 * T_INV);
    g_B[r]  = (n > 0.f) ? (S * T_INV) / n : 0.f;
    if (n <= 0.f) g_H[r] = -1.f;   // sentinel: row contributes 0

    __shared__ unsigned sm[256];
    sm[threadIdx.x] = fkey(t0);
    __syncthreads();
    for (int s = 128; s; s >>= 1) {
        if (threadIdx.x < s) sm[threadIdx.x] = max(sm[threadIdx.x], sm[threadIdx.x + s]);
        __syncthreads();
    }
    if (threadIdx.x == 0) atomicMax(&g_Gkey, sm[0]);
}

// ---------------------------------------------------------------------------
// Kernel 4: final loss
// ---------------------------------------------------------------------------
__global__ void finalize_kernel(float* __restrict__ out) {
    __shared__ float sh[1024];
    int tid = threadIdx.x;
    float G = funkey(g_Gkey) * T_INV;
    float eG = __expf(-G);
    float sum = 0.f;
    for (int r = tid; r < BATCH; r += 1024) {
        float H = g_H[r];
        if (H >= 0.f)
            sum += __logf(g_D1[r] + eG * H) - g_B[r];
    }
    sh[tid] = sum;
    __syncthreads();
    for (int s = 512; s; s >>= 1) {
        if (tid < s) sh[tid] += sh[tid + s];
        __syncthreads();
    }
    if (tid == 0) out[0] = sh[0] / (float)BATCH;
}

// ---------------------------------------------------------------------------
extern "C" void kernel_launch(void* const* d_in, const int* in_sizes, int n_in,
                              void* d_out, int out_size) {
    const float* x   = (const float*)d_in[0];
    const int*   idx = (const int*)d_in[1];
    float*       out = (float*)d_out;

    cudaFuncSetAttribute(sim_kernel, cudaFuncAttributeMaxDynamicSharedMemorySize,
                         SMEM_BYTES);

    prep_idx_kernel<<<1, 256>>>(idx);
    normalize_kernel<<<BATCH, 128>>>(x);
    sim_kernel<<<NTILE, 256, SMEM_BYTES>>>();
    merge_kernel<<<BATCH / 256, 256>>>();
    finalize_kernel<<<1, 1024>>>(out);
}

// round 8
// speedup vs baseline: 1.4763x; 1.1198x over previous
#include <cuda_runtime.h>
#include <cuda_bf16.h>
#include <math_constants.h>
#include <cstdint>

#define BATCH 8192
#define DIM   512
#define T_INV 14.2857142857142857f  // 1/0.07

#define NSTRIP 64                  // 64 strips of 128 rows
#define NTILE  (NSTRIP * (NSTRIP + 1) / 2)   // 2080 upper-tri tiles
#define NSLOT  64
#define PSTRIDE 12                 // floats per partial record (9 used, f4-aligned)

#define MT     128
#define NT     128
#define KC     64                  // bf16 halves per chunk
#define NCHUNK (DIM / KC)          // 8

#define PITCHH 72                  // halves per SMEM row (144B; conflict-free frags)
#define AB_HALVES (MT * PITCHH)            // 9216 halves per operand
#define STAGE_HALVES (2 * AB_HALVES)
#define STAGE_BYTES  (STAGE_HALVES * 2)    // 36864
#define SMEM_BYTES   (2 * STAGE_BYTES)     // 73728 (C tile + partials alias)
#define CPITCH 132

// ---------------- static scratch ----------------
__device__ __nv_bfloat16 g_fb[BATCH * DIM];
__device__ int   g_idx[BATCH];
__device__ unsigned g_Gkey;
__device__ float g_part[(size_t)BATCH * NSLOT * PSTRIDE];  // per (row, slot) partials
__device__ float g_D1[BATCH], g_H[BATCH], g_B[BATCH];

// ---------------- helpers ----------------
__device__ __forceinline__ uint32_t smem_u32(const void* p) {
    uint32_t a;
    asm("{ .reg .u64 t; cvta.to.shared.u64 t, %1; cvt.u32.u64 %0, t; }" : "=r"(a) : "l"(p));
    return a;
}
__device__ __forceinline__ void cpa16(uint32_t dst, const void* src) {
    asm volatile("cp.async.cg.shared.global [%0], [%1], 16;" :: "r"(dst), "l"(src));
}
#define CP_COMMIT() asm volatile("cp.async.commit_group;" ::: "memory")
#define CP_WAIT1()  asm volatile("cp.async.wait_group 1;" ::: "memory")
#define CP_WAIT0()  asm volatile("cp.async.wait_group 0;" ::: "memory")

__device__ __forceinline__ void ldsm_x4(uint32_t* r, uint32_t addr) {
    asm volatile("ldmatrix.sync.aligned.m8n8.x4.shared.b16 {%0,%1,%2,%3}, [%4];"
                 : "=r"(r[0]), "=r"(r[1]), "=r"(r[2]), "=r"(r[3]) : "r"(addr));
}
__device__ __forceinline__ void mma16(float* c, const uint32_t* a, uint32_t b0, uint32_t b1) {
    asm volatile(
        "mma.sync.aligned.m16n8k16.row.col.f32.bf16.bf16.f32 "
        "{%0,%1,%2,%3}, {%4,%5,%6,%7}, {%8,%9}, {%0,%1,%2,%3};"
        : "+f"(c[0]), "+f"(c[1]), "+f"(c[2]), "+f"(c[3])
        : "r"(a[0]), "r"(a[1]), "r"(a[2]), "r"(a[3]), "r"(b0), "r"(b1));
}

__device__ __forceinline__ unsigned fkey(float f) {
    unsigned u = __float_as_uint(f);
    return (u & 0x80000000u) ? ~u : (u | 0x80000000u);
}
__device__ __forceinline__ float funkey(unsigned k) {
    unsigned u = (k & 0x80000000u) ? (k & 0x7FFFFFFFu) : ~k;
    return __uint_as_float(u);
}
__device__ __forceinline__ void top5_ins(float v, float& t0, float& t1, float& t2,
                                         float& t3, float& t4) {
    if (v > t4) {
        float w = v, tmp;
        if (w > t0) { tmp = t0; t0 = w; w = tmp; }
        if (w > t1) { tmp = t1; t1 = w; w = tmp; }
        if (w > t2) { tmp = t2; t2 = w; w = tmp; }
        if (w > t3) { tmp = t3; t3 = w; w = tmp; }
        t4 = w;
    }
}

// ---------------------------------------------------------------------------
// Kernel 0: dtype-agnostic index canonicalization (int32 vs int64) + G reset
// ---------------------------------------------------------------------------
__global__ void prep_idx_kernel(const int* __restrict__ raw) {
    __shared__ int sh[256];
    int tid = threadIdx.x;
    int acc = 0;
    for (int i = tid; i < BATCH / 2; i += 256) acc |= raw[2 * i + 1];
    sh[tid] = acc;
    __syncthreads();
    for (int s = 128; s; s >>= 1) { if (tid < s) sh[tid] |= sh[tid + s]; __syncthreads(); }
    bool is64 = (sh[0] == 0);
    for (int i = tid; i < BATCH; i += 256) g_idx[i] = is64 ? raw[2 * i] : raw[i];
    if (tid == 0) g_Gkey = 0u;
}

// ---------------------------------------------------------------------------
// Kernel 1: L2 normalize + round to bf16 (rn)
// ---------------------------------------------------------------------------
__global__ void normalize_kernel(const float* __restrict__ x) {
    int row = blockIdx.x;
    int t = threadIdx.x;
    float4 v = ((const float4*)(x + row * DIM))[t];
    float ss = v.x * v.x + v.y * v.y + v.z * v.z + v.w * v.w;
    #pragma unroll
    for (int o = 16; o; o >>= 1) ss += __shfl_xor_sync(0xffffffffu, ss, o);
    __shared__ float ws[4];
    if ((t & 31) == 0) ws[t >> 5] = ss;
    __syncthreads();
    float inv = 1.0f / fmaxf(sqrtf(ws[0] + ws[1] + ws[2] + ws[3]), 1e-12f);
    __nv_bfloat162 p0 = __floats2bfloat162_rn(v.x * inv, v.y * inv);
    __nv_bfloat162 p1 = __floats2bfloat162_rn(v.z * inv, v.w * inv);
    uint2 w;
    w.x = *(uint32_t*)&p0;
    w.y = *(uint32_t*)&p1;
    ((uint2*)(g_fb + row * DIM))[t] = w;
}

// ---------------------------------------------------------------------------
// Kernel 2: symmetric-triangle HMMA bf16 GEMM (ldmatrix frags) + dual scans
//   grid = 2080 upper-tri tiles; block = 256 (8 warps, 4x2 of 32x64 tiles)
// ---------------------------------------------------------------------------
__device__ __forceinline__ void prefetch_chunk(uint32_t s_base, int st, int row0,
                                               int col0, int kb, int tid) {
    const uint32_t stf = s_base + st * STAGE_BYTES;
    #pragma unroll
    for (int i = tid; i < MT * 8; i += 256) {       // A: 128 rows x 8 segs of 16B
        int r = i >> 3, sg = i & 7;
        cpa16(stf + (r * PITCHH + sg * 8) * 2, g_fb + (row0 + r) * DIM + kb + sg * 8);
    }
    #pragma unroll
    for (int i = tid; i < NT * 8; i += 256) {       // B
        int r = i >> 3, sg = i & 7;
        cpa16(stf + AB_HALVES * 2 + (r * PITCHH + sg * 8) * 2,
              g_fb + (col0 + r) * DIM + kb + sg * 8);
    }
    CP_COMMIT();
}

__global__ __launch_bounds__(256, 2)
void sim_kernel() {
    extern __shared__ float smem[];
    const uint32_t s_base = smem_u32(smem);
    const int tid  = threadIdx.x;
    const int lane = tid & 31, warp = tid >> 5;

    // decode blockIdx -> (I, J) with I <= J  (b = J(J+1)/2 + I)
    const int b = blockIdx.x;
    int J = (int)((sqrtf(8.0f * b + 1.0f) - 1.0f) * 0.5f);
    while ((J + 1) * (J + 2) / 2 <= b) ++J;
    while (J * (J + 1) / 2 > b) --J;
    const int I = b - J * (J + 1) / 2;
    const int row0 = I * MT;
    const int col0 = J * NT;

    const int wm = warp >> 1, wn = warp & 1;
    const int qg = lane >> 2, qt = lane & 3;

    // ldmatrix per-lane byte offsets within a stage
    uint32_t aoff[2], boff[4];
    {
        const int l7 = lane & 7, l8 = (lane >> 3) & 1, l16 = (lane >> 4) & 1;
        #pragma unroll
        for (int i = 0; i < 2; i++) {
            int rowA = wm * 32 + i * 16 + l8 * 8 + l7;
            aoff[i] = (uint32_t)((rowA * PITCHH + l16 * 8) * 2);
        }
        #pragma unroll
        for (int jp = 0; jp < 4; jp++) {
            int nB = wn * 64 + jp * 16 + l16 * 8 + l7;
            boff[jp] = (uint32_t)(AB_HALVES * 2 + (nB * PITCHH + l8 * 8) * 2);
        }
    }

    float acc[2][8][4];
    #pragma unroll
    for (int i = 0; i < 2; i++)
        #pragma unroll
        for (int j = 0; j < 8; j++)
            #pragma unroll
            for (int q = 0; q < 4; q++) acc[i][j][q] = 0.f;

    prefetch_chunk(s_base, 0, row0, col0, 0, tid);
    prefetch_chunk(s_base, 1, row0, col0, KC, tid);

    for (int c = 0; c < NCHUNK; c++) {
        const int st = c & 1;
        if (c >= NCHUNK - 2) { CP_WAIT0(); } else { CP_WAIT1(); }
        __syncthreads();
        const uint32_t stb = s_base + st * STAGE_BYTES;
        #pragma unroll
        for (int ks = 0; ks < 4; ks++) {
            const uint32_t ko = ks * 32;       // 16 halves = 32 bytes per k16 step
            uint32_t a0[4], a1[4], bb[4][4];
            ldsm_x4(a0, stb + aoff[0] + ko);
            ldsm_x4(a1, stb + aoff[1] + ko);
            #pragma unroll
            for (int jp = 0; jp < 4; jp++) ldsm_x4(bb[jp], stb + boff[jp] + ko);
            #pragma unroll
            for (int jp = 0; jp < 4; jp++) {
                mma16(acc[0][2 * jp],     a0, bb[jp][0], bb[jp][1]);
                mma16(acc[1][2 * jp],     a1, bb[jp][0], bb[jp][1]);
                mma16(acc[0][2 * jp + 1], a0, bb[jp][2], bb[jp][3]);
                mma16(acc[1][2 * jp + 1], a1, bb[jp][2], bb[jp][3]);
            }
        }
        __syncthreads();
        if (c + 2 < NCHUNK)
            prefetch_chunk(s_base, st, row0, col0, (c + 2) * KC, tid);
    }

    // stage C tile (aliases stage buffers; all mma reads complete)
    float* Cs = smem;
    float* Ps = smem + 128 * CPITCH;    // 128 x 9 partial-exchange floats
    #pragma unroll
    for (int i = 0; i < 2; i++) {
        #pragma unroll
        for (int j = 0; j < 8; j++) {
            int r = wm * 32 + i * 16 + qg;
            int cc = wn * 64 + j * 8 + 2 * qt;
            Cs[r * CPITCH + cc]           = acc[i][j][0];
            Cs[r * CPITCH + cc + 1]       = acc[i][j][1];
            Cs[(r + 8) * CPITCH + cc]     = acc[i][j][2];
            Cs[(r + 8) * CPITCH + cc + 1] = acc[i][j][3];
        }
    }
    __syncthreads();

    const int sidx = tid & 127, shalf = tid >> 7;

    // ---- row scan: stats for strip I rows over strip J cols -> slot J ----
    {
        const int myrow = row0 + sidx;
        const int myidx = g_idx[myrow];
        const float* crow = Cs + sidx * CPITCH + shalf * 64;
        const int colbase = col0 + shalf * 64;
        float lS = 0.f, lP = 0.f, ln = 0.f, lrm = -CUDART_INF_F;
        float l0 = -CUDART_INF_F, l1 = -CUDART_INF_F, l2 = -CUDART_INF_F,
              l3 = -CUDART_INF_F, l4 = -CUDART_INF_F;
        for (int cc = 0; cc < 64; cc++) {
            int gcol = colbase + cc;
            if (gcol == myrow) continue;   // only possible on diagonal tiles
            float v = crow[cc];
            top5_ins(v, l0, l1, l2, l3, l4);
            if (__ldg(&g_idx[gcol]) == myidx) {
                ln += 1.0f; lS += v; lrm = fmaxf(lrm, v);
                lP += __expf(v * T_INV);
            }
        }
        if (shalf) {
            float* pp = Ps + sidx * 9;
            pp[0] = lS; pp[1] = lP; pp[2] = ln; pp[3] = lrm;
            pp[4] = l0; pp[5] = l1; pp[6] = l2; pp[7] = l3; pp[8] = l4;
        }
        __syncthreads();
        if (!shalf) {
            const float* pp = Ps + sidx * 9;
            lS += pp[0]; lP += pp[1]; ln += pp[2]; lrm = fmaxf(lrm, pp[3]);
            top5_ins(pp[4], l0, l1, l2, l3, l4);
            top5_ins(pp[5], l0, l1, l2, l3, l4);
            top5_ins(pp[6], l0, l1, l2, l3, l4);
            top5_ins(pp[7], l0, l1, l2, l3, l4);
            top5_ins(pp[8], l0, l1, l2, l3, l4);
            float* gp = g_part + ((size_t)myrow * NSLOT + J) * PSTRIDE;
            gp[0] = lS; gp[1] = lP; gp[2] = ln; gp[3] = lrm;
            gp[4] = l0; gp[5] = l1; gp[6] = l2; gp[7] = l3; gp[8] = l4;
        }
    }

    if (I == J) return;   // diagonal: row scan fully covers; no col scan

    __syncthreads();      // Ps reuse

    // ---- col scan: stats for strip J rows over strip I cols -> slot I ----
    {
        const int myrow = col0 + sidx;          // global row owned via tile col
        const int myidx = g_idx[myrow];
        const int rbase = shalf * 64;
        float lS = 0.f, lP = 0.f, ln = 0.f, lrm = -CUDART_INF_F;
        float l0 = -CUDART_INF_F, l1 = -CUDART_INF_F, l2 = -CUDART_INF_F,
              l3 = -CUDART_INF_F, l4 = -CUDART_INF_F;
        for (int rr = 0; rr < 64; rr++) {
            float v = Cs[(rbase + rr) * CPITCH + sidx];
            top5_ins(v, l0, l1, l2, l3, l4);
            if (__ldg(&g_idx[row0 + rbase + rr]) == myidx) {
                ln += 1.0f; lS += v; lrm = fmaxf(lrm, v);
                lP += __expf(v * T_INV);
            }
        }
        if (shalf) {
            float* pp = Ps + sidx * 9;
            pp[0] = lS; pp[1] = lP; pp[2] = ln; pp[3] = lrm;
            pp[4] = l0; pp[5] = l1; pp[6] = l2; pp[7] = l3; pp[8] = l4;
        }
        __syncthreads();
        if (!shalf) {
            const float* pp = Ps + sidx * 9;
            lS += pp[0]; lP += pp[1]; ln += pp[2]; lrm = fmaxf(lrm, pp[3]);
            top5_ins(pp[4], l0, l1, l2, l3, l4);
            top5_ins(pp[5], l0, l1, l2, l3, l4);
            top5_ins(pp[6], l0, l1, l2, l3, l4);
            top5_ins(pp[7], l0, l1, l2, l3, l4);
            top5_ins(pp[8], l0, l1, l2, l3, l4);
            float* gp = g_part + ((size_t)myrow * NSLOT + I) * PSTRIDE;
            gp[0] = lS; gp[1] = lP; gp[2] = ln; gp[3] = lrm;
            gp[4] = l0; gp[5] = l1; gp[6] = l2; gp[7] = l3; gp[8] = l4;
        }
    }
}

// ---------------------------------------------------------------------------
// Kernel 3: parallel merge — 8 threads/row, shfl butterfly; global max
// ---------------------------------------------------------------------------
__global__ void merge_kernel() {
    const int tid = threadIdx.x;
    const int lane = tid & 31;
    const int sub = lane & 7;                 // slot sub-group within row
    const int r = blockIdx.x * 32 + (tid >> 3);

    const float4* base = (const float4*)(g_part + (size_t)r * NSLOT * PSTRIDE);
    float S = 0.f, P = 0.f, n = 0.f, rm = -CUDART_INF_F;
    float t0 = -CUDART_INF_F, t1 = -CUDART_INF_F, t2 = -CUDART_INF_F,
          t3 = -CUDART_INF_F, t4 = -CUDART_INF_F;
    #pragma unroll
    for (int q = 0; q < 8; q++) {
        int s = sub + q * 8;
        float4 a = base[s * 3 + 0];
        float4 c = base[s * 3 + 1];
        float4 d = base[s * 3 + 2];
        S += a.x; P += a.y; n += a.z; rm = fmaxf(rm, a.w);
        top5_ins(c.x, t0, t1, t2, t3, t4);
        top5_ins(c.y, t0, t1, t2, t3, t4);
        top5_ins(c.z, t0, t1, t2, t3, t4);
        top5_ins(c.w, t0, t1, t2, t3, t4);
        top5_ins(d.x, t0, t1, t2, t3, t4);
    }
    // deterministic butterfly across the 8 lanes of this row
    #pragma unroll
    for (int o = 1; o < 8; o <<= 1) {
        S += __shfl_xor_sync(0xffffffffu, S, o);
        P += __shfl_xor_sync(0xffffffffu, P, o);
        n += __shfl_xor_sync(0xffffffffu, n, o);
        rm = fmaxf(rm, __shfl_xor_sync(0xffffffffu, rm, o));
        float m0 = __shfl_xor_sync(0xffffffffu, t0, o);
        float m1 = __shfl_xor_sync(0xffffffffu, t1, o);
        float m2 = __shfl_xor_sync(0xffffffffu, t2, o);
        float m3 = __shfl_xor_sync(0xffffffffu, t3, o);
        float m4 = __shfl_xor_sync(0xffffffffu, t4, o);
        top5_ins(m0, t0, t1, t2, t3, t4);
        top5_ins(m1, t0, t1, t2, t3, t4);
        top5_ins(m2, t0, t1, t2, t3, t4);
        top5_ins(m3, t0, t1, t2, t3, t4);
        top5_ins(m4, t0, t1, t2, t3, t4);
    }
    if (sub == 0) {
        g_D1[r] = (n > 0.f) ? __expf(-rm * T_INV) * P : 0.f;
        float H = __expf(t0 * T_INV) + __expf(t1 * T_INV) + __expf(t2 * T_INV) +
                  __expf(t3 * T_INV) + __expf(t4 * T_INV);
        g_H[r] = (n > 0.f) ? H : -1.f;     // sentinel: row contributes 0
        g_B[r] = (n > 0.f) ? (S * T_INV) / n : 0.f;
    }

    // global max of t0 (all 8 lanes of a row agree post-butterfly)
    __shared__ unsigned sm[256];
    sm[tid] = fkey(t0);
    __syncthreads();
    for (int s = 128; s; s >>= 1) {
        if (tid < s) sm[tid] = max(sm[tid], sm[tid + s]);
        __syncthreads();
    }
    if (tid == 0) atomicMax(&g_Gkey, sm[0]);
}

// ---------------------------------------------------------------------------
// Kernel 4: final loss
// ---------------------------------------------------------------------------
__global__ void finalize_kernel(float* __restrict__ out) {
    __shared__ float sh[1024];
    int tid = threadIdx.x;
    float G = funkey(g_Gkey) * T_INV;
    float eG = __expf(-G);
    float sum = 0.f;
    for (int r = tid; r < BATCH; r += 1024) {
        float H = g_H[r];
        if (H >= 0.f)
            sum += __logf(g_D1[r] + eG * H) - g_B[r];
    }
    sh[tid] = sum;
    __syncthreads();
    for (int s = 512; s; s >>= 1) {
        if (tid < s) sh[tid] += sh[tid + s];
        __syncthreads();
    }
    if (tid == 0) out[0] = sh[0] / (float)BATCH;
}

// ---------------------------------------------------------------------------
extern "C" void kernel_launch(void* const* d_in, const int* in_sizes, int n_in,
                              void* d_out, int out_size) {
    const float* x   = (const float*)d_in[0];
    const int*   idx = (const int*)d_in[1];
    float*       out = (float*)d_out;

    cudaFuncSetAttribute(sim_kernel, cudaFuncAttributeMaxDynamicSharedMemorySize,
                         SMEM_BYTES);

    prep_idx_kernel<<<1, 256>>>(idx);
    normalize_kernel<<<BATCH, 128>>>(x);
    sim_kernel<<<NTILE, 256, SMEM_BYTES>>>();
    merge_kernel<<<BATCH / 32, 256>>>();
    finalize_kernel<<<1, 1024>>>(out);
}